// round 1
// baseline (speedup 1.0000x reference)
#include <cuda_runtime.h>
#include <math.h>

// Problem constants
#define B_    16
#define NPTS  2048
#define PCTR  256
#define KNB   32
#define HW    1920          // 24*80
#define INFEA 64
#define MTOT  131072        // B_*PCTR*KNB
#define EPSBN 1e-5f
#define DIST_ 0.5f

// ---------------- scratch (static device globals; zero-initialized at load) ----------------
__device__ float g_X0[80 * MTOT];    // layer-1 input, channels 67..79 stay zero forever
__device__ float g_Y1[64 * MTOT];
__device__ float g_Y2[128 * MTOT];
__device__ float g_Y3[128 * MTOT];
__device__ float g_Y4[256 * MTOT];
__device__ int   g_idx[MTOT];
__device__ int   g_ridx[MTOT];
__device__ float g_vmask[B_ * PCTR];
__device__ float g_W1p[64 * 80];
__device__ float g_sum[4][256];
__device__ float g_sq[4][256];
__device__ float g_sc[4][256];
__device__ float g_sh[4][256];

// ---------------- kernel 1: depth-ball query (+ zero stats) ----------------
__global__ void k_idx(const float* __restrict__ pc,
                      const float* __restrict__ npc,
                      const int*   __restrict__ qv1)
{
    __shared__ float zs[NPTS];
    __shared__ int   stage[8][32];
    const int b   = blockIdx.x;
    const int tid = threadIdx.x;

    if (b == 0) {
        float* ps = &g_sum[0][0];
        float* pq = &g_sq[0][0];
        for (int i = tid; i < 4 * 256; i += 256) { ps[i] = 0.f; pq[i] = 0.f; }
    }
    for (int i = tid; i < NPTS; i += 256) zs[i] = pc[(b * 3 + 2) * NPTS + i];
    __syncthreads();

    const int w = tid >> 5, lane = tid & 31;
    for (int jj = 0; jj < 32; jj++) {
        const int j = w * 32 + jj;
        const float cz = npc[(b * 3 + 2) * PCTR + j];
        int cnt = 0;
        for (int c = 0; c < NPTS / 32; c++) {
            const int n = c * 32 + lane;
            const bool hit = fabsf(zs[n] - cz) < DIST_;
            const unsigned bal = __ballot_sync(0xffffffffu, hit);
            if (hit) {
                const int pos = cnt + __popc(bal & ((1u << lane) - 1u));
                if (pos < 32) stage[w][pos] = n;
            }
            cnt += __popc(bal);
            if (cnt >= 32) break;
        }
        __syncwarp();
        const int cc = min(cnt, 32);
        const int first = (cnt > 0) ? stage[w][0] : 0;
        const int v = (lane < cc) ? stage[w][lane] : first;
        const int gbase = (b * PCTR + j) * KNB;
        g_idx[gbase + lane]  = v;
        g_ridx[gbase + lane] = qv1[b * NPTS + v];
        if (lane == 0) g_vmask[b * PCTR + j] = (cnt > 0) ? 1.f : 0.f;
        __syncwarp();
    }
}

// ---------------- kernel: pad W1 (64x67 -> 64x80) ----------------
__global__ void k_padw1(const float* __restrict__ w1)
{
    for (int e = threadIdx.x; e < 64 * 80; e += 256) {
        const int r = e / 80, c = e % 80;
        g_W1p[e] = (c < 67) ? w1[r * 67 + c] : 0.f;
    }
}

// ---------------- kernel 2: gather X0 + write rgb channels into out ----------------
__global__ void k_gather(const float* __restrict__ pc,
                         const float* __restrict__ feat,
                         const float* __restrict__ img1,
                         const float* __restrict__ img2,
                         const float* __restrict__ npc,
                         float* __restrict__ out)
{
    __shared__ int   s_idx[32];
    __shared__ int   s_rid[32];
    __shared__ float s_np[3];
    __shared__ float s_vm;
    const int g = blockIdx.x;           // b*PCTR + j
    const int b = g >> 8;
    const int j = g & 255;
    const int t = threadIdx.x;
    const int mbase = g * KNB;

    if (t < 32) { s_idx[t] = g_idx[mbase + t]; s_rid[t] = g_ridx[mbase + t]; }
    if (t >= 32 && t < 35) s_np[t - 32] = npc[(b * 3 + (t - 32)) * PCTR + j];
    if (t == 40) s_vm = g_vmask[g];
    __syncthreads();

    const float vm = s_vm;
    const long ob = (long)b * (640 * 8192) + (long)j * 32;

    // pc channels (3 x 32)
    if (t < 96) {
        const int c = t >> 5, k = t & 31;
        g_X0[c * MTOT + mbase + k] = pc[(b * 3 + c) * NPTS + s_idx[k]] - s_np[c];
    }
    // feat channels (64 x 32)
    for (int e = t; e < INFEA * 32; e += 256) {
        const int c = e >> 5, k = e & 31;
        g_X0[(3 + c) * MTOT + mbase + k] = feat[(b * INFEA + c) * NPTS + s_idx[k]];
    }
    // rgb1 -> out channels [64,128)
    for (int e = t; e < 64 * 32; e += 256) {
        const int c = e >> 5, k = e & 31;
        out[ob + (long)(64 + c) * 8192 + k] = img1[(b * 64 + c) * HW + s_rid[k]] * vm;
    }
    // rgb2 -> out channels [256,384)
    for (int e = t; e < 128 * 32; e += 256) {
        const int c = e >> 5, k = e & 31;
        out[ob + (long)(256 + c) * 8192 + k] = img2[(b * 128 + c) * HW + s_rid[k]] * vm;
    }
}

// ---------------- fp32 GEMM: Y[BMgrid][M] = W @ normrelu(X), fused channel stats ----------------
template <int BM, int CIN, bool NORM_IN>
__global__ void k_gemm(const float* __restrict__ W,
                       const float* __restrict__ X,
                       float* __restrict__ Y,
                       const float* __restrict__ isc,
                       const float* __restrict__ ish,
                       float* __restrict__ osum,
                       float* __restrict__ osq)
{
    constexpr int BN = 128, BK = 8;
    constexpr int THREADS = (BM / 8) * 16;
    __shared__ float Ws[BK][BM];
    __shared__ float Xs[BK][BN];
    __shared__ float red[BM];

    const int tid = threadIdx.x;
    const int bn0 = blockIdx.x * BN;
    const int bm0 = blockIdx.y * BM;
    const int tn = tid & 15;
    const int tm = tid >> 4;

    float acc[8][8];
#pragma unroll
    for (int i = 0; i < 8; i++)
#pragma unroll
        for (int j = 0; j < 8; j++) acc[i][j] = 0.f;

    for (int k0 = 0; k0 < CIN; k0 += BK) {
        for (int e = tid; e < BM * BK; e += THREADS) {
            const int r = e >> 3, kk = e & 7;
            Ws[kk][r] = W[(bm0 + r) * CIN + k0 + kk];
        }
        for (int q = tid; q < BK * (BN / 4); q += THREADS) {
            const int kk = q >> 5, c4 = q & 31;
            float4 v = *(const float4*)&X[(k0 + kk) * MTOT + bn0 + c4 * 4];
            if (NORM_IN) {
                const float s = isc[k0 + kk], t = ish[k0 + kk];
                v.x = fmaxf(v.x * s + t, 0.f);
                v.y = fmaxf(v.y * s + t, 0.f);
                v.z = fmaxf(v.z * s + t, 0.f);
                v.w = fmaxf(v.w * s + t, 0.f);
            }
            *(float4*)&Xs[kk][c4 * 4] = v;
        }
        __syncthreads();
#pragma unroll
        for (int kk = 0; kk < BK; kk++) {
            float a[8], bb[8];
#pragma unroll
            for (int i = 0; i < 8; i++) a[i] = Ws[kk][tm * 8 + i];
#pragma unroll
            for (int j = 0; j < 8; j++) bb[j] = Xs[kk][tn * 8 + j];
#pragma unroll
            for (int i = 0; i < 8; i++)
#pragma unroll
                for (int j = 0; j < 8; j++) acc[i][j] = fmaf(a[i], bb[j], acc[i][j]);
        }
        __syncthreads();
    }

    // write Y (raw pre-BN)
#pragma unroll
    for (int i = 0; i < 8; i++) {
        const int row = bm0 + tm * 8 + i;
        float* yp = &Y[row * MTOT + bn0 + tn * 8];
        *(float4*)yp       = make_float4(acc[i][0], acc[i][1], acc[i][2], acc[i][3]);
        *(float4*)(yp + 4) = make_float4(acc[i][4], acc[i][5], acc[i][6], acc[i][7]);
    }

    // per-channel sum / sumsq
    for (int e = tid; e < BM; e += THREADS) red[e] = 0.f;
    __syncthreads();
#pragma unroll
    for (int i = 0; i < 8; i++) {
        float s = 0.f;
#pragma unroll
        for (int j = 0; j < 8; j++) s += acc[i][j];
        atomicAdd(&red[tm * 8 + i], s);
    }
    __syncthreads();
    for (int e = tid; e < BM; e += THREADS) atomicAdd(&osum[bm0 + e], red[e]);
    __syncthreads();
    for (int e = tid; e < BM; e += THREADS) red[e] = 0.f;
    __syncthreads();
#pragma unroll
    for (int i = 0; i < 8; i++) {
        float s = 0.f;
#pragma unroll
        for (int j = 0; j < 8; j++) s += acc[i][j] * acc[i][j];
        atomicAdd(&red[tm * 8 + i], s);
    }
    __syncthreads();
    for (int e = tid; e < BM; e += THREADS) atomicAdd(&osq[bm0 + e], red[e]);
}

// ---------------- stats -> (scale, shift) ----------------
__global__ void k_stats(int layer, const float* __restrict__ gam,
                        const float* __restrict__ bet, int C)
{
    const int c = threadIdx.x;
    if (c < C) {
        const float m = g_sum[layer][c] * (1.f / (float)MTOT);
        const float v = g_sq[layer][c] * (1.f / (float)MTOT) - m * m;
        const float s = gam[c] * rsqrtf(v + EPSBN);
        g_sc[layer][c] = s;
        g_sh[layer][c] = bet[c] - m * s;
    }
}

// ---------------- normalize + relu + valid-mask -> out channels [cbase, cbase+C) ----------------
__global__ void k_norm_out(const float* __restrict__ Y, int layer, int C, int cbase,
                           float* __restrict__ out)
{
    const int total4 = C * (MTOT / 4);
    for (int e = blockIdx.x * blockDim.x + threadIdx.x; e < total4;
         e += gridDim.x * blockDim.x) {
        const int c  = e / (MTOT / 4);
        const int m4 = e - c * (MTOT / 4);
        const int m  = m4 * 4;
        float4 y = *(const float4*)&Y[c * MTOT + m];
        const float s = g_sc[layer][c], t = g_sh[layer][c];
        const float vm = g_vmask[m >> 5];
        const int b = m >> 13;
        const int rem = m & 8191;
        float4 o;
        o.x = fmaxf(y.x * s + t, 0.f) * vm;
        o.y = fmaxf(y.y * s + t, 0.f) * vm;
        o.z = fmaxf(y.z * s + t, 0.f) * vm;
        o.w = fmaxf(y.w * s + t, 0.f) * vm;
        *(float4*)&out[(long)b * (640 * 8192) + (long)(cbase + c) * 8192 + rem] = o;
    }
}

// ---------------- launch ----------------
extern "C" void kernel_launch(void* const* d_in, const int* in_sizes, int n_in,
                              void* d_out, int out_size)
{
    const float* pc   = (const float*)d_in[0];
    const float* feat = (const float*)d_in[1];
    const float* img1 = (const float*)d_in[2];
    const float* img2 = (const float*)d_in[3];
    /* d_in[4] = P (unused by reference) */
    const int*   qv1  = (const int*)d_in[5];
    const float* npc  = (const float*)d_in[6];
    const float* w1 = (const float*)d_in[7];
    const float* g1 = (const float*)d_in[8];
    const float* b1 = (const float*)d_in[9];
    const float* w2 = (const float*)d_in[10];
    const float* g2 = (const float*)d_in[11];
    const float* b2 = (const float*)d_in[12];
    const float* w3 = (const float*)d_in[13];
    const float* g3 = (const float*)d_in[14];
    const float* b3 = (const float*)d_in[15];
    const float* w4 = (const float*)d_in[16];
    const float* g4 = (const float*)d_in[17];
    const float* b4 = (const float*)d_in[18];
    float* out = (float*)d_out;

    float *pX0, *pY1, *pY2, *pY3, *pY4, *pW1p, *pSum, *pSq, *pSc, *pSh;
    cudaGetSymbolAddress((void**)&pX0,  g_X0);
    cudaGetSymbolAddress((void**)&pY1,  g_Y1);
    cudaGetSymbolAddress((void**)&pY2,  g_Y2);
    cudaGetSymbolAddress((void**)&pY3,  g_Y3);
    cudaGetSymbolAddress((void**)&pY4,  g_Y4);
    cudaGetSymbolAddress((void**)&pW1p, g_W1p);
    cudaGetSymbolAddress((void**)&pSum, g_sum);
    cudaGetSymbolAddress((void**)&pSq,  g_sq);
    cudaGetSymbolAddress((void**)&pSc,  g_sc);
    cudaGetSymbolAddress((void**)&pSh,  g_sh);

    k_idx<<<B_, 256>>>(pc, npc, qv1);
    k_padw1<<<1, 256>>>(w1);
    k_gather<<<B_ * PCTR, 256>>>(pc, feat, img1, img2, npc, out);

    const int GX = MTOT / 128;

    // L1: 64 <- 80(pad of 67)
    k_gemm<64, 80, false><<<dim3(GX, 1), 128>>>(pW1p, pX0, pY1, nullptr, nullptr,
                                                pSum + 0 * 256, pSq + 0 * 256);
    k_stats<<<1, 256>>>(0, g1, b1, 64);
    k_norm_out<<<2048, 256>>>(pY1, 0, 64, 0, out);

    // L2: 128 <- 64
    k_gemm<128, 64, true><<<dim3(GX, 1), 256>>>(w2, pY1, pY2, pSc + 0 * 256, pSh + 0 * 256,
                                                pSum + 1 * 256, pSq + 1 * 256);
    k_stats<<<1, 256>>>(1, g2, b2, 128);
    k_norm_out<<<2048, 256>>>(pY2, 1, 128, 128, out);

    // L3: 128 <- 128
    k_gemm<128, 128, true><<<dim3(GX, 1), 256>>>(w3, pY2, pY3, pSc + 1 * 256, pSh + 1 * 256,
                                                 pSum + 2 * 256, pSq + 2 * 256);
    k_stats<<<1, 256>>>(2, g3, b3, 128);

    // L4: 256 <- 128
    k_gemm<128, 128, true><<<dim3(GX, 2), 256>>>(w4, pY3, pY4, pSc + 2 * 256, pSh + 2 * 256,
                                                 pSum + 3 * 256, pSq + 3 * 256);
    k_stats<<<1, 256>>>(3, g4, b4, 256);
    k_norm_out<<<2048, 256>>>(pY4, 3, 256, 384, out);
}